// round 15
// baseline (speedup 1.0000x reference)
#include <cuda_runtime.h>
#include <cuda_fp16.h>
#include <cstdint>
#include <math.h>

// ---------------- problem constants ----------------
#define NE   16
#define HD   1024
#define ID   512
#define ISD  2048
#define NTOK 8192
#define SLOT_CAP (NTOK*2 + NE*128)   // 18432
#define MTILES   (SLOT_CAP/128)      // 144
#define STAGES   3
#define PH2      72                   // smem row stride in halves (144B)
#define A_H      (128*PH2)            // 9216 halves (A region: 128 rows)
#define STG_H    (256*PH2)            // 18432 halves (A 128 + B 128 rows)
#define STG_BYTES (STG_H*2)           // 36864
#define SMEM_DYN (STAGES*STG_BYTES)   // 110592  -> 2 CTAs/SM

// ---------------- scratch (device globals) ----------------
__device__ __half g_hbufh[(size_t)SLOT_CAP * ID];    // silu(g)*u per slot (fp16)
__device__ float  g_dres [(size_t)SLOT_CAP * HD];    // expert down output (fp32)
__device__ __half g_gbufh[(size_t)NTOK * ISD];       // shared silu(g)*u (fp16)
__device__ __half g_xh   [(size_t)NTOK * HD];        // x in fp16
__device__ __half g_guph [(size_t)NE * 2 * ID * HD]; // interleaved g/u expert weights (fp16)
__device__ __half g_downh[(size_t)NE * HD * ID];     // fp16
__device__ __half g_sguh [(size_t)2 * ISD * HD];     // interleaved shared g/u weights (fp16)
__device__ __half g_sdph [(size_t)HD * ISD];         // fp16
__device__ int   g_tok_idx[SLOT_CAP];
__device__ int   g_slot_of[NTOK*2];
__device__ int   g_sel[NTOK*2];
__device__ float g_w[NTOK*2];
__device__ float g_sgate[NTOK];
__device__ int   g_cnt[NE];
__device__ float g_probsum[NE];
__device__ int   g_fill[NE];
__device__ int   g_eoff[NE+1];
__device__ int   g_blk_e[MTILES];
__device__ int   g_total;

// ---------------- K0: init ----------------
__global__ void init_kernel() {
    int i = blockIdx.x * blockDim.x + threadIdx.x;
    if (i < SLOT_CAP) g_tok_idx[i] = -1;
    if (i < NE) { g_cnt[i] = 0; g_probsum[i] = 0.f; g_fill[i] = 0; }
}

// ---------------- K1: router (one warp per token, fp32 exact) ----------------
__global__ void router_kernel(const float* __restrict__ x,
                              const float* __restrict__ gw,
                              const float* __restrict__ segw, int N) {
    int warp = (blockIdx.x * blockDim.x + threadIdx.x) >> 5;
    int lane = threadIdx.x & 31;
    __shared__ float s_ps[NE];
    __shared__ int   s_cnt[NE];
    if (threadIdx.x < NE) { s_ps[threadIdx.x] = 0.f; s_cnt[threadIdx.x] = 0; }
    __syncthreads();

    if (warp < N) {
        float acc[17];
        #pragma unroll
        for (int j = 0; j < 17; j++) acc[j] = 0.f;
        const float* xr = x + (size_t)warp * HD;
        for (int k = lane; k < HD; k += 32) {
            float xv = __ldg(xr + k);
            #pragma unroll
            for (int j = 0; j < NE; j++) acc[j] += xv * __ldg(gw + j * HD + k);
            acc[16] += xv * __ldg(segw + k);
        }
        #pragma unroll
        for (int j = 0; j < 17; j++) {
            #pragma unroll
            for (int o = 16; o > 0; o >>= 1)
                acc[j] += __shfl_xor_sync(0xffffffffu, acc[j], o);
        }
        float mx = acc[0];
        #pragma unroll
        for (int j = 1; j < NE; j++) mx = fmaxf(mx, acc[j]);
        float p[NE]; float s = 0.f;
        #pragma unroll
        for (int j = 0; j < NE; j++) { p[j] = expf(acc[j] - mx); s += p[j]; }
        float inv = 1.f / s;
        #pragma unroll
        for (int j = 0; j < NE; j++) p[j] *= inv;
        int a0 = 0;
        #pragma unroll
        for (int j = 1; j < NE; j++) if (p[j] > p[a0]) a0 = j;
        int a1 = (a0 == 0) ? 1 : 0;
        #pragma unroll
        for (int j = 0; j < NE; j++) if (j != a0 && p[j] > p[a1]) a1 = j;
        float ww = p[a0] + p[a1];
        if (lane == 0) {
            g_sel[warp*2]   = a0;  g_sel[warp*2+1] = a1;
            g_w[warp*2]     = p[a0] / ww;
            g_w[warp*2+1]   = p[a1] / ww;
            g_sgate[warp]   = 1.f / (1.f + expf(-acc[16]));
            atomicAdd(&s_cnt[a0], 1); atomicAdd(&s_cnt[a1], 1);
        }
        if (lane < NE) atomicAdd(&s_ps[lane], p[lane]);
    }
    __syncthreads();
    if (threadIdx.x < NE) {
        atomicAdd(&g_probsum[threadIdx.x], s_ps[threadIdx.x]);
        atomicAdd(&g_cnt[threadIdx.x], s_cnt[threadIdx.x]);
    }
}

// ---------------- K2: offsets + aux loss ----------------
__global__ void offsets_kernel(float* __restrict__ out, long aux_index, int N) {
    if (threadIdx.x == 0 && blockIdx.x == 0) {
        int off = 0;
        for (int e = 0; e < NE; e++) {
            g_eoff[e] = off;
            off += ((g_cnt[e] + 127) / 128) * 128;
        }
        g_eoff[NE] = off;
        g_total = off;
        for (int e = 0; e < NE; e++)
            for (int t = g_eoff[e] / 128; t < g_eoff[e+1] / 128; t++)
                g_blk_e[t] = e;
        float aux = 0.f;
        for (int e = 0; e < NE; e++)
            aux += ((float)g_cnt[e] / (float)(N * 2)) * (g_probsum[e] / (float)N);
        out[aux_index] = (float)NE * aux;
    }
}

// ---------------- K3: slot assignment ----------------
__global__ void assign_kernel(int N) {
    int t = blockIdx.x * blockDim.x + threadIdx.x;
    if (t < N) {
        #pragma unroll
        for (int i = 0; i < 2; i++) {
            int e = g_sel[t*2 + i];
            int pos = atomicAdd(&g_fill[e], 1);
            int slot = g_eoff[e] + pos;
            g_tok_idx[slot] = t;
            g_slot_of[t*2 + i] = slot;
        }
    }
}

// ---------------- conversion kernels (fp32 -> fp16 RN) ----------------
__global__ void tohalf4(const float4* __restrict__ src, __half* __restrict__ dst, long n4) {
    long i = blockIdx.x * (long)blockDim.x + threadIdx.x;
    if (i < n4) {
        float4 v = src[i];
        __half2 h0 = __floats2half2_rn(v.x, v.y);
        __half2 h1 = __floats2half2_rn(v.z, v.w);
        *(uint2*)(dst + i * 4) = make_uint2(*(unsigned*)&h0, *(unsigned*)&h1);
    }
}

// gup [E][2I][H] -> interleaved fp16: dst row 2j = gate_j, 2j+1 = up_j (per expert)
__global__ void interleave_gup_kernel(const float* __restrict__ src, __half* __restrict__ dst) {
    long i4 = blockIdx.x * (long)blockDim.x + threadIdx.x;
    long total4 = (long)NE * 2 * ID * HD / 4;
    if (i4 >= total4) return;
    long i = i4 * 4;
    long e = i >> 20;
    int  r = (int)((i >> 10) & 1023);
    int  k = (int)(i & 1023);
    int  j = r >> 1;
    int  sr = (r & 1) ? (ID + j) : j;
    float4 v = *(const float4*)(src + (e << 20) + (size_t)sr * HD + k);
    __half2 h0 = __floats2half2_rn(v.x, v.y);
    __half2 h1 = __floats2half2_rn(v.z, v.w);
    *(uint2*)(dst + i) = make_uint2(*(unsigned*)&h0, *(unsigned*)&h1);
}

// sgp/sup [IS][H] -> interleaved fp16 [2*IS][H]
__global__ void interleave_sgu_kernel(const float* __restrict__ g, const float* __restrict__ u,
                                      __half* __restrict__ dst) {
    long i4 = blockIdx.x * (long)blockDim.x + threadIdx.x;
    long total4 = (long)2 * ISD * HD / 4;
    if (i4 >= total4) return;
    long i = i4 * 4;
    int r = (int)(i >> 10);
    int k = (int)(i & 1023);
    int j = r >> 1;
    const float* s = (r & 1) ? u : g;
    float4 v = *(const float4*)(s + (size_t)j * HD + k);
    __half2 h0 = __floats2half2_rn(v.x, v.y);
    __half2 h1 = __floats2half2_rn(v.z, v.w);
    *(uint2*)(dst + i) = make_uint2(*(unsigned*)&h0, *(unsigned*)&h1);
}

// ---------------- fp16 mma.sync GEMM (dual-job): C[M,N] = A[M,K] @ B[N,K]^T ----
// CTA tile 128x128, warp tile 64x32 (8 warps), ktile K=64 (4x k16).
// 3-stage 16B-cp.async pipeline; one thread fills one full smem row per ktile
// (8x16B chunks = 64 halves). Stride PH2=72 halves: store phases hit banks
// 4r mod 32 (distinct per 8 lanes) and non-trans ldmatrix is conflict-free.
// 2 CTAs/SM. Two jobs packed per launch; block picks job from blockIdx.x vs nb0.
struct Job {
    const __half* A; const __half* B; void* C;
    int K, ldc;
    const int* rm;      // row gather (-1 => zero row) or null
    const int* be;      // per-m-tile expert index or null
    long es;            // expert B stride
    int mode;           // 0 plain f32, 1 fused silu->half, 2 fused final combine->f32
    int mdev;           // 1: M = g_total (skip tiles beyond)
    int nx, ny;         // tile grid
};

__global__ __launch_bounds__(256, 2)
void gemm_dual(Job j0, Job j1, int nb0)
{
    Job jb; int q;
    if ((int)blockIdx.x < nb0) { jb = j0; q = blockIdx.x; }
    else                       { jb = j1; q = blockIdx.x - nb0; }
    const int bx = q % jb.nx;
    const int by = q / jb.nx;
    const int m0 = bx * 128;
    if (jb.mdev && m0 >= g_total) return;
    const int n0 = by * 128;
    const int K = jb.K, ldc = jb.ldc, mode = jb.mode;

    extern __shared__ __half dsm[];
    const uint32_t sbase = (uint32_t)__cvta_generic_to_shared(dsm);

    const int t    = threadIdx.x;
    const int lane = t & 31;
    const int wid  = t >> 5;
    const int wm0  = (wid & 1) * 64;
    const int wn0  = (wid >> 1) * 32;
    const int tg   = lane & 3;
    const int gid  = lane >> 2;

    // fetch mapping: thread t owns one smem row (A row t if t<128, else B row t-128),
    // 64 halves per ktile as 8x16B chunks.
    const __half* src;
    unsigned csz = 16u;
    uint32_t dstb;
    if (t < 128) {
        if (jb.rm) {
            int tok = __ldg(&jb.rm[m0 + t]);
            csz = (tok < 0) ? 0u : 16u;
            src = jb.A + (size_t)(tok < 0 ? 0 : tok) * K;
        } else {
            src = jb.A + (size_t)(m0 + t) * K;
        }
        dstb = sbase + (uint32_t)(t * PH2) * 2u;
    } else {
        const __half* Bp = jb.be ? (jb.B + (size_t)__ldg(&jb.be[bx]) * jb.es) : jb.B;
        src  = Bp + (size_t)(n0 + (t - 128)) * K;
        dstb = sbase + (uint32_t)(A_H + (t - 128) * PH2) * 2u;
    }

    const int KT = K >> 6;             // ktile = 64 halves

    // ldmatrix lane address bases
    const int alr = lane & 15;
    const int alc = (lane >> 4) * 8;
    uint32_t aLdBase[4];
    #pragma unroll
    for (int mi = 0; mi < 4; mi++)
        aLdBase[mi] = sbase + (uint32_t)((wm0 + mi * 16 + alr) * PH2 + alc) * 2u;
    const int blr = (lane & 7) + ((lane >> 4) * 8);
    const int blc = ((lane >> 3) & 1) * 8;
    uint32_t bLdBase[2];
    #pragma unroll
    for (int nj = 0; nj < 2; nj++)
        bLdBase[nj] = sbase + (uint32_t)(A_H + (wn0 + nj * 16 + blr) * PH2 + blc) * 2u;

    float c[4][4][4];
    #pragma unroll
    for (int mi = 0; mi < 4; mi++)
        #pragma unroll
        for (int ni = 0; ni < 4; ni++)
            #pragma unroll
            for (int qq = 0; qq < 4; qq++) c[mi][ni][qq] = 0.f;

    auto fetch = [&](int kt_f, int slot) {
        uint32_t st = (uint32_t)slot * STG_BYTES;
        unsigned koff = (unsigned)(kt_f * 64);
        #pragma unroll
        for (int cch = 0; cch < 8; cch++) {
            asm volatile("cp.async.cg.shared.global [%0], [%1], 16, %2;"
                         :: "r"(dstb + st + cch * 16), "l"(src + koff + cch * 8), "r"(csz));
        }
    };

    fetch(0, 0);
    asm volatile("cp.async.commit_group;");
    fetch(1, 1);
    asm volatile("cp.async.commit_group;");

    int cslot = 0, fslot = 2;
    for (int kt = 0; kt < KT; kt++) {
        asm volatile("cp.async.wait_group %0;" :: "n"(STAGES - 2));
        __syncthreads();
        int ft = kt + STAGES - 1;
        if (ft < KT) fetch(ft, fslot);
        asm volatile("cp.async.commit_group;");
        if (++fslot == STAGES) fslot = 0;

        const uint32_t stoff = (uint32_t)cslot * STG_BYTES;
        #pragma unroll
        for (int ks = 0; ks < 4; ks++) {
            const uint32_t kb = stoff + (uint32_t)ks * 32u;
            unsigned a[4][4], b[4][2];
            #pragma unroll
            for (int mi = 0; mi < 4; mi++)
                asm volatile("ldmatrix.sync.aligned.m8n8.x4.shared.b16 {%0,%1,%2,%3}, [%4];"
                             : "=r"(a[mi][0]), "=r"(a[mi][1]), "=r"(a[mi][2]), "=r"(a[mi][3])
                             : "r"(aLdBase[mi] + kb));
            #pragma unroll
            for (int nj = 0; nj < 2; nj++)
                asm volatile("ldmatrix.sync.aligned.m8n8.x4.shared.b16 {%0,%1,%2,%3}, [%4];"
                             : "=r"(b[2*nj][0]), "=r"(b[2*nj][1]),
                               "=r"(b[2*nj+1][0]), "=r"(b[2*nj+1][1])
                             : "r"(bLdBase[nj] + kb));
            #pragma unroll
            for (int mi = 0; mi < 4; mi++)
                #pragma unroll
                for (int ni = 0; ni < 4; ni++)
                    asm volatile(
                        "mma.sync.aligned.m16n8k16.row.col.f32.f16.f16.f32 "
                        "{%0,%1,%2,%3}, {%4,%5,%6,%7}, {%8,%9}, {%0,%1,%2,%3};\n"
                        : "+f"(c[mi][ni][0]), "+f"(c[mi][ni][1]),
                          "+f"(c[mi][ni][2]), "+f"(c[mi][ni][3])
                        : "r"(a[mi][0]), "r"(a[mi][1]), "r"(a[mi][2]), "r"(a[mi][3]),
                          "r"(b[ni][0]), "r"(b[ni][1]));
        }
        if (++cslot == STAGES) cslot = 0;
    }

    // ---------------- epilogue ----------------
    const int tg2 = tg * 2;
    if (mode == 1) {                      // fused silu -> half output at col/2
        __half* Ch = (__half*)jb.C;
        #pragma unroll
        for (int mi = 0; mi < 4; mi++) {
            int r = m0 + wm0 + mi * 16 + gid;
            #pragma unroll
            for (int ni = 0; ni < 4; ni++) {
                int cc = (n0 + wn0 + ni * 8 + tg2) >> 1;
                float g0 = c[mi][ni][0], u0 = c[mi][ni][1];
                float g1 = c[mi][ni][2], u1 = c[mi][ni][3];
                float hv0 = (g0 / (1.f + __expf(-g0))) * u0;
                float hv1 = (g1 / (1.f + __expf(-g1))) * u1;
                Ch[(size_t)r * ldc + cc]       = __float2half_rn(hv0);
                Ch[(size_t)(r + 8) * ldc + cc] = __float2half_rn(hv1);
            }
        }
    } else if (mode == 2) {               // fused final combine -> f32 out
        float* Cf = (float*)jb.C;
        #pragma unroll
        for (int mi = 0; mi < 4; mi++) {
            int r0 = m0 + wm0 + mi * 16 + gid;
            int r1 = r0 + 8;
            float w00 = g_w[2*r0], w01 = g_w[2*r0+1], sg0 = g_sgate[r0];
            int   s00 = g_slot_of[2*r0], s01 = g_slot_of[2*r0+1];
            float w10 = g_w[2*r1], w11 = g_w[2*r1+1], sg1 = g_sgate[r1];
            int   s10 = g_slot_of[2*r1], s11 = g_slot_of[2*r1+1];
            #pragma unroll
            for (int ni = 0; ni < 4; ni++) {
                int cc = n0 + wn0 + ni * 8 + tg2;
                float2 d00 = *(const float2*)&g_dres[(size_t)s00 * HD + cc];
                float2 d01 = *(const float2*)&g_dres[(size_t)s01 * HD + cc];
                float2 o0;
                o0.x = c[mi][ni][0] * sg0 + w00 * d00.x + w01 * d01.x;
                o0.y = c[mi][ni][1] * sg0 + w00 * d00.y + w01 * d01.y;
                *(float2*)(Cf + (size_t)r0 * ldc + cc) = o0;
                float2 d10 = *(const float2*)&g_dres[(size_t)s10 * HD + cc];
                float2 d11 = *(const float2*)&g_dres[(size_t)s11 * HD + cc];
                float2 o1;
                o1.x = c[mi][ni][2] * sg1 + w10 * d10.x + w11 * d11.x;
                o1.y = c[mi][ni][3] * sg1 + w10 * d10.y + w11 * d11.y;
                *(float2*)(Cf + (size_t)r1 * ldc + cc) = o1;
            }
        }
    } else {                              // plain f32
        float* Cf = (float*)jb.C;
        #pragma unroll
        for (int mi = 0; mi < 4; mi++) {
            #pragma unroll
            for (int ni = 0; ni < 4; ni++) {
                int r  = m0 + wm0 + mi * 16 + gid;
                int cc = n0 + wn0 + ni * 8 + tg2;
                *(float2*)(Cf + (size_t)r * ldc + cc)       = make_float2(c[mi][ni][0], c[mi][ni][1]);
                *(float2*)(Cf + (size_t)(r + 8) * ldc + cc) = make_float2(c[mi][ni][2], c[mi][ni][3]);
            }
        }
    }
}

// ---------------- launch ----------------
extern "C" void kernel_launch(void* const* d_in, const int* in_sizes, int n_in,
                              void* d_out, int out_size) {
    const float* x    = (const float*)d_in[0];
    const float* gw   = (const float*)d_in[1];
    const float* gup  = (const float*)d_in[2];
    const float* down = (const float*)d_in[3];
    const float* sgp  = (const float*)d_in[4];
    const float* sup  = (const float*)d_in[5];
    const float* sdp  = (const float*)d_in[6];
    const float* segw = (const float*)d_in[7];
    float* out = (float*)d_out;
    int N = in_sizes[0] / HD;   // 8192

    __half *p_hbuf, *p_gbuf, *p_xh, *p_guph, *p_downh, *p_sguh, *p_sdph;
    float *p_dres;
    int *p_tok_idx, *p_blk_e;
    cudaGetSymbolAddress((void**)&p_hbuf,   g_hbufh);
    cudaGetSymbolAddress((void**)&p_dres,   g_dres);
    cudaGetSymbolAddress((void**)&p_gbuf,   g_gbufh);
    cudaGetSymbolAddress((void**)&p_xh,     g_xh);
    cudaGetSymbolAddress((void**)&p_guph,   g_guph);
    cudaGetSymbolAddress((void**)&p_downh,  g_downh);
    cudaGetSymbolAddress((void**)&p_sguh,   g_sguh);
    cudaGetSymbolAddress((void**)&p_sdph,   g_sdph);
    cudaGetSymbolAddress((void**)&p_tok_idx, g_tok_idx);
    cudaGetSymbolAddress((void**)&p_blk_e,  g_blk_e);

    cudaFuncSetAttribute(gemm_dual, cudaFuncAttributeMaxDynamicSharedMemorySize, SMEM_DYN);

    init_kernel<<<(SLOT_CAP + 255) / 256, 256>>>();
    router_kernel<<<(N + 7) / 8, 256>>>(x, gw, segw, N);
    offsets_kernel<<<1, 32>>>(out, (long)out_size - 1, N);
    assign_kernel<<<(N + 255) / 256, 256>>>(N);

    // conversions to fp16 (g/u row interleaving for fused silu)
    interleave_gup_kernel<<<(int)((long)NE*2*ID*HD/4/256), 256>>>(gup, p_guph);
    tohalf4<<<(int)((long)NE*HD*ID/4/256), 256>>>((const float4*)down, p_downh, (long)NE*HD*ID/4);
    interleave_sgu_kernel<<<(int)((long)2*ISD*HD/4/256), 256>>>(sgp, sup, p_sguh);
    tohalf4<<<(int)((long)HD*ISD/4/256), 256>>>((const float4*)sdp, p_sdph, (long)HD*ISD/4);
    tohalf4<<<(int)((long)N*HD/4/256), 256>>>((const float4*)x, p_xh, (long)N*HD/4);

    Job jz = {};  jz.nx = 1; jz.ny = 0;   // empty second job

    // Phase A: shared gate/up (64x32) + expert gate_up (144x8), both fused-silu
    Job jsgu = { p_xh, p_sguh, p_gbuf, HD, ISD, nullptr, nullptr, 0, 1, 0, N/128, ISD*2/128 };
    Job jegu = { p_xh, p_guph, p_hbuf, HD, ID,  p_tok_idx, p_blk_e, (long)2*ID*HD, 1, 1, MTILES, 2*ID/128 };
    int nbA0 = jsgu.nx * jsgu.ny;                 // 2048
    gemm_dual<<<nbA0 + jegu.nx * jegu.ny, 256, SMEM_DYN>>>(jsgu, jegu, nbA0);

    // Phase B: expert down (144x8) -> dres
    Job jed = { p_hbuf, p_downh, p_dres, ID, HD, nullptr, p_blk_e, (long)HD*ID, 0, 1, MTILES, HD/128 };
    gemm_dual<<<jed.nx * jed.ny, 256, SMEM_DYN>>>(jed, jz, jed.nx * jed.ny);

    // Phase C: shared down + fused final combine -> out
    Job jsd = { p_gbuf, p_sdph, out, ISD, HD, nullptr, nullptr, 0, 2, 0, N/128, HD/128 };
    gemm_dual<<<jsd.nx * jsd.ny, 256, SMEM_DYN>>>(jsd, jz, jsd.nx * jsd.ny);
}

// round 16
// speedup vs baseline: 1.5044x; 1.5044x over previous
#include <cuda_runtime.h>
#include <cuda_fp16.h>
#include <cstdint>
#include <math.h>

// ---------------- problem constants ----------------
#define NE   16
#define HD   1024
#define ID   512
#define ISD  2048
#define NTOK 8192
#define SLOT_CAP (NTOK*2 + NE*128)   // 18432
#define MTILES   (SLOT_CAP/128)      // 144
#define STAGES   3
#define PH2      72                   // smem row stride in halves (144B)
#define A_H      (128*PH2)            // 9216 halves (A region: 128 rows)
#define STG_H    (256*PH2)            // 18432 halves (A 128 + B 128 rows)
#define STG_BYTES (STG_H*2)           // 36864
#define SMEM_DYN (STAGES*STG_BYTES)   // 110592  -> 2 CTAs/SM

// ---------------- scratch (device globals) ----------------
__device__ __half g_hbufh[(size_t)SLOT_CAP * ID];    // silu(g)*u per slot (fp16)
__device__ float  g_dres [(size_t)SLOT_CAP * HD];    // expert down output (fp32)
__device__ __half g_gbufh[(size_t)NTOK * ISD];       // shared silu(g)*u (fp16)
__device__ __half g_xh   [(size_t)NTOK * HD];        // x in fp16
__device__ __half g_guph [(size_t)NE * 2 * ID * HD]; // interleaved g/u expert weights (fp16)
__device__ __half g_downh[(size_t)NE * HD * ID];     // fp16
__device__ __half g_sguh [(size_t)2 * ISD * HD];     // interleaved shared g/u weights (fp16)
__device__ __half g_sdph [(size_t)HD * ISD];         // fp16
__device__ int   g_tok_idx[SLOT_CAP];
__device__ int   g_slot_of[NTOK*2];
__device__ int   g_sel[NTOK*2];
__device__ float g_w[NTOK*2];
__device__ float g_sgate[NTOK];
__device__ int   g_cnt[NE];
__device__ float g_probsum[NE];
__device__ int   g_fill[NE];
__device__ int   g_eoff[NE+1];
__device__ int   g_blk_e[MTILES];
__device__ int   g_total;

// ---------------- K0: init ----------------
__global__ void init_kernel() {
    int i = blockIdx.x * blockDim.x + threadIdx.x;
    if (i < SLOT_CAP) g_tok_idx[i] = -1;
    if (i < NE) { g_cnt[i] = 0; g_probsum[i] = 0.f; g_fill[i] = 0; }
}

// ---------------- K1: router (one warp per token, fp32 exact) ----------------
__global__ void router_kernel(const float* __restrict__ x,
                              const float* __restrict__ gw,
                              const float* __restrict__ segw, int N) {
    int warp = (blockIdx.x * blockDim.x + threadIdx.x) >> 5;
    int lane = threadIdx.x & 31;
    __shared__ float s_ps[NE];
    __shared__ int   s_cnt[NE];
    if (threadIdx.x < NE) { s_ps[threadIdx.x] = 0.f; s_cnt[threadIdx.x] = 0; }
    __syncthreads();

    if (warp < N) {
        float acc[17];
        #pragma unroll
        for (int j = 0; j < 17; j++) acc[j] = 0.f;
        const float* xr = x + (size_t)warp * HD;
        for (int k = lane; k < HD; k += 32) {
            float xv = __ldg(xr + k);
            #pragma unroll
            for (int j = 0; j < NE; j++) acc[j] += xv * __ldg(gw + j * HD + k);
            acc[16] += xv * __ldg(segw + k);
        }
        #pragma unroll
        for (int j = 0; j < 17; j++) {
            #pragma unroll
            for (int o = 16; o > 0; o >>= 1)
                acc[j] += __shfl_xor_sync(0xffffffffu, acc[j], o);
        }
        float mx = acc[0];
        #pragma unroll
        for (int j = 1; j < NE; j++) mx = fmaxf(mx, acc[j]);
        float p[NE]; float s = 0.f;
        #pragma unroll
        for (int j = 0; j < NE; j++) { p[j] = expf(acc[j] - mx); s += p[j]; }
        float inv = 1.f / s;
        #pragma unroll
        for (int j = 0; j < NE; j++) p[j] *= inv;
        int a0 = 0;
        #pragma unroll
        for (int j = 1; j < NE; j++) if (p[j] > p[a0]) a0 = j;
        int a1 = (a0 == 0) ? 1 : 0;
        #pragma unroll
        for (int j = 0; j < NE; j++) if (j != a0 && p[j] > p[a1]) a1 = j;
        float ww = p[a0] + p[a1];
        if (lane == 0) {
            g_sel[warp*2]   = a0;  g_sel[warp*2+1] = a1;
            g_w[warp*2]     = p[a0] / ww;
            g_w[warp*2+1]   = p[a1] / ww;
            g_sgate[warp]   = 1.f / (1.f + expf(-acc[16]));
            atomicAdd(&s_cnt[a0], 1); atomicAdd(&s_cnt[a1], 1);
        }
        if (lane < NE) atomicAdd(&s_ps[lane], p[lane]);
    }
    __syncthreads();
    if (threadIdx.x < NE) {
        atomicAdd(&g_probsum[threadIdx.x], s_ps[threadIdx.x]);
        atomicAdd(&g_cnt[threadIdx.x], s_cnt[threadIdx.x]);
    }
}

// ---------------- K2: offsets + aux loss ----------------
__global__ void offsets_kernel(float* __restrict__ out, long aux_index, int N) {
    if (threadIdx.x == 0 && blockIdx.x == 0) {
        int off = 0;
        for (int e = 0; e < NE; e++) {
            g_eoff[e] = off;
            off += ((g_cnt[e] + 127) / 128) * 128;
        }
        g_eoff[NE] = off;
        g_total = off;
        for (int e = 0; e < NE; e++)
            for (int t = g_eoff[e] / 128; t < g_eoff[e+1] / 128; t++)
                g_blk_e[t] = e;
        float aux = 0.f;
        for (int e = 0; e < NE; e++)
            aux += ((float)g_cnt[e] / (float)(N * 2)) * (g_probsum[e] / (float)N);
        out[aux_index] = (float)NE * aux;
    }
}

// ---------------- K3: slot assignment ----------------
__global__ void assign_kernel(int N) {
    int t = blockIdx.x * blockDim.x + threadIdx.x;
    if (t < N) {
        #pragma unroll
        for (int i = 0; i < 2; i++) {
            int e = g_sel[t*2 + i];
            int pos = atomicAdd(&g_fill[e], 1);
            int slot = g_eoff[e] + pos;
            g_tok_idx[slot] = t;
            g_slot_of[t*2 + i] = slot;
        }
    }
}

// ---------------- conversion kernels (fp32 -> fp16 RN) ----------------
__global__ void tohalf4(const float4* __restrict__ src, __half* __restrict__ dst, long n4) {
    long i = blockIdx.x * (long)blockDim.x + threadIdx.x;
    if (i < n4) {
        float4 v = src[i];
        __half2 h0 = __floats2half2_rn(v.x, v.y);
        __half2 h1 = __floats2half2_rn(v.z, v.w);
        *(uint2*)(dst + i * 4) = make_uint2(*(unsigned*)&h0, *(unsigned*)&h1);
    }
}

// gup [E][2I][H] -> interleaved fp16: dst row 2j = gate_j, 2j+1 = up_j (per expert)
__global__ void interleave_gup_kernel(const float* __restrict__ src, __half* __restrict__ dst) {
    long i4 = blockIdx.x * (long)blockDim.x + threadIdx.x;
    long total4 = (long)NE * 2 * ID * HD / 4;
    if (i4 >= total4) return;
    long i = i4 * 4;
    long e = i >> 20;
    int  r = (int)((i >> 10) & 1023);
    int  k = (int)(i & 1023);
    int  j = r >> 1;
    int  sr = (r & 1) ? (ID + j) : j;
    float4 v = *(const float4*)(src + (e << 20) + (size_t)sr * HD + k);
    __half2 h0 = __floats2half2_rn(v.x, v.y);
    __half2 h1 = __floats2half2_rn(v.z, v.w);
    *(uint2*)(dst + i) = make_uint2(*(unsigned*)&h0, *(unsigned*)&h1);
}

// sgp/sup [IS][H] -> interleaved fp16 [2*IS][H]
__global__ void interleave_sgu_kernel(const float* __restrict__ g, const float* __restrict__ u,
                                      __half* __restrict__ dst) {
    long i4 = blockIdx.x * (long)blockDim.x + threadIdx.x;
    long total4 = (long)2 * ISD * HD / 4;
    if (i4 >= total4) return;
    long i = i4 * 4;
    int r = (int)(i >> 10);
    int k = (int)(i & 1023);
    int j = r >> 1;
    const float* s = (r & 1) ? u : g;
    float4 v = *(const float4*)(s + (size_t)j * HD + k);
    __half2 h0 = __floats2half2_rn(v.x, v.y);
    __half2 h1 = __floats2half2_rn(v.z, v.w);
    *(uint2*)(dst + i) = make_uint2(*(unsigned*)&h0, *(unsigned*)&h1);
}

// ---------------- fp16 mma.sync GEMM (dual-job): C[M,N] = A[M,K] @ B[N,K]^T ----
// CTA tile 128x128, warp tile 64x32 (8 warps), ktile K=64 (4x k16).
// 3-stage 16B-cp.async pipeline; one thread fills one full smem row per ktile
// (8x16B chunks = 64 halves). Stride PH2=72 halves: store phases hit banks
// 4r mod 32 (distinct per 8 lanes) and non-trans ldmatrix is conflict-free.
// 2 CTAs/SM. Two jobs packed per launch; block picks job from blockIdx.x vs nb0.
struct Job {
    const __half* A; const __half* B; void* C;
    int K, ldc;
    const int* rm;      // row gather (-1 => zero row) or null
    const int* be;      // per-m-tile expert index or null
    long es;            // expert B stride
    int mode;           // 0 plain f32, 1 fused silu->half, 2 fused final combine->f32
    int mdev;           // 1: M = g_total (skip tiles beyond)
    int nx, ny;         // tile grid
};

__global__ __launch_bounds__(256, 2)
void gemm_dual(Job j0, Job j1, int nb0)
{
    Job jb; int q;
    if ((int)blockIdx.x < nb0) { jb = j0; q = blockIdx.x; }
    else                       { jb = j1; q = blockIdx.x - nb0; }
    const int bx = q % jb.nx;
    const int by = q / jb.nx;
    const int m0 = bx * 128;
    if (jb.mdev && m0 >= g_total) return;
    const int n0 = by * 128;
    const int K = jb.K, ldc = jb.ldc, mode = jb.mode;

    extern __shared__ __half dsm[];
    const uint32_t sbase = (uint32_t)__cvta_generic_to_shared(dsm);

    const int t    = threadIdx.x;
    const int lane = t & 31;
    const int wid  = t >> 5;
    const int wm0  = (wid & 1) * 64;
    const int wn0  = (wid >> 1) * 32;
    const int tg   = lane & 3;
    const int gid  = lane >> 2;

    // fetch mapping: thread t owns one smem row (A row t if t<128, else B row t-128),
    // 64 halves per ktile as 8x16B chunks.
    const __half* src;
    unsigned csz = 16u;
    uint32_t dstb;
    if (t < 128) {
        if (jb.rm) {
            int tok = __ldg(&jb.rm[m0 + t]);
            csz = (tok < 0) ? 0u : 16u;
            src = jb.A + (size_t)(tok < 0 ? 0 : tok) * K;
        } else {
            src = jb.A + (size_t)(m0 + t) * K;
        }
        dstb = sbase + (uint32_t)(t * PH2) * 2u;
    } else {
        const __half* Bp = jb.be ? (jb.B + (size_t)__ldg(&jb.be[bx]) * jb.es) : jb.B;
        src  = Bp + (size_t)(n0 + (t - 128)) * K;
        dstb = sbase + (uint32_t)(A_H + (t - 128) * PH2) * 2u;
    }

    const int KT = K >> 6;             // ktile = 64 halves

    // ldmatrix lane address bases
    const int alr = lane & 15;
    const int alc = (lane >> 4) * 8;
    uint32_t aLdBase[4];
    #pragma unroll
    for (int mi = 0; mi < 4; mi++)
        aLdBase[mi] = sbase + (uint32_t)((wm0 + mi * 16 + alr) * PH2 + alc) * 2u;
    const int blr = (lane & 7) + ((lane >> 4) * 8);
    const int blc = ((lane >> 3) & 1) * 8;
    uint32_t bLdBase[2];
    #pragma unroll
    for (int nj = 0; nj < 2; nj++)
        bLdBase[nj] = sbase + (uint32_t)(A_H + (wn0 + nj * 16 + blr) * PH2 + blc) * 2u;

    float c[4][4][4];
    #pragma unroll
    for (int mi = 0; mi < 4; mi++)
        #pragma unroll
        for (int ni = 0; ni < 4; ni++)
            #pragma unroll
            for (int qq = 0; qq < 4; qq++) c[mi][ni][qq] = 0.f;

    auto fetch = [&](int kt_f, int slot) {
        uint32_t st = (uint32_t)slot * STG_BYTES;
        unsigned koff = (unsigned)(kt_f * 64);
        #pragma unroll
        for (int cch = 0; cch < 8; cch++) {
            asm volatile("cp.async.cg.shared.global [%0], [%1], 16, %2;"
                         :: "r"(dstb + st + cch * 16), "l"(src + koff + cch * 8), "r"(csz));
        }
    };

    fetch(0, 0);
    asm volatile("cp.async.commit_group;");
    fetch(1, 1);
    asm volatile("cp.async.commit_group;");

    int cslot = 0, fslot = 2;
    for (int kt = 0; kt < KT; kt++) {
        asm volatile("cp.async.wait_group %0;" :: "n"(STAGES - 2));
        __syncthreads();
        int ft = kt + STAGES - 1;
        if (ft < KT) fetch(ft, fslot);
        asm volatile("cp.async.commit_group;");
        if (++fslot == STAGES) fslot = 0;

        const uint32_t stoff = (uint32_t)cslot * STG_BYTES;
        #pragma unroll
        for (int ks = 0; ks < 4; ks++) {
            const uint32_t kb = stoff + (uint32_t)ks * 32u;
            unsigned a[4][4], b[4][2];
            #pragma unroll
            for (int mi = 0; mi < 4; mi++)
                asm volatile("ldmatrix.sync.aligned.m8n8.x4.shared.b16 {%0,%1,%2,%3}, [%4];"
                             : "=r"(a[mi][0]), "=r"(a[mi][1]), "=r"(a[mi][2]), "=r"(a[mi][3])
                             : "r"(aLdBase[mi] + kb));
            #pragma unroll
            for (int nj = 0; nj < 2; nj++)
                asm volatile("ldmatrix.sync.aligned.m8n8.x4.shared.b16 {%0,%1,%2,%3}, [%4];"
                             : "=r"(b[2*nj][0]), "=r"(b[2*nj][1]),
                               "=r"(b[2*nj+1][0]), "=r"(b[2*nj+1][1])
                             : "r"(bLdBase[nj] + kb));
            #pragma unroll
            for (int mi = 0; mi < 4; mi++)
                #pragma unroll
                for (int ni = 0; ni < 4; ni++)
                    asm volatile(
                        "mma.sync.aligned.m16n8k16.row.col.f32.f16.f16.f32 "
                        "{%0,%1,%2,%3}, {%4,%5,%6,%7}, {%8,%9}, {%0,%1,%2,%3};\n"
                        : "+f"(c[mi][ni][0]), "+f"(c[mi][ni][1]),
                          "+f"(c[mi][ni][2]), "+f"(c[mi][ni][3])
                        : "r"(a[mi][0]), "r"(a[mi][1]), "r"(a[mi][2]), "r"(a[mi][3]),
                          "r"(b[ni][0]), "r"(b[ni][1]));
        }
        if (++cslot == STAGES) cslot = 0;
    }

    // ---------------- epilogue ----------------
    const int tg2 = tg * 2;
    if (mode == 1) {                      // fused silu -> half output at col/2
        __half* Ch = (__half*)jb.C;
        #pragma unroll
        for (int mi = 0; mi < 4; mi++) {
            int r = m0 + wm0 + mi * 16 + gid;
            #pragma unroll
            for (int ni = 0; ni < 4; ni++) {
                int cc = (n0 + wn0 + ni * 8 + tg2) >> 1;
                float g0 = c[mi][ni][0], u0 = c[mi][ni][1];
                float g1 = c[mi][ni][2], u1 = c[mi][ni][3];
                float hv0 = (g0 / (1.f + __expf(-g0))) * u0;
                float hv1 = (g1 / (1.f + __expf(-g1))) * u1;
                Ch[(size_t)r * ldc + cc]       = __float2half_rn(hv0);
                Ch[(size_t)(r + 8) * ldc + cc] = __float2half_rn(hv1);
            }
        }
    } else if (mode == 2) {               // fused final combine -> f32 out
        float* Cf = (float*)jb.C;
        #pragma unroll
        for (int mi = 0; mi < 4; mi++) {
            int r0 = m0 + wm0 + mi * 16 + gid;
            int r1 = r0 + 8;
            float w00 = g_w[2*r0], w01 = g_w[2*r0+1], sg0 = g_sgate[r0];
            int   s00 = g_slot_of[2*r0], s01 = g_slot_of[2*r0+1];
            float w10 = g_w[2*r1], w11 = g_w[2*r1+1], sg1 = g_sgate[r1];
            int   s10 = g_slot_of[2*r1], s11 = g_slot_of[2*r1+1];
            #pragma unroll
            for (int ni = 0; ni < 4; ni++) {
                int cc = n0 + wn0 + ni * 8 + tg2;
                float2 d00 = *(const float2*)&g_dres[(size_t)s00 * HD + cc];
                float2 d01 = *(const float2*)&g_dres[(size_t)s01 * HD + cc];
                float2 o0;
                o0.x = c[mi][ni][0] * sg0 + w00 * d00.x + w01 * d01.x;
                o0.y = c[mi][ni][1] * sg0 + w00 * d00.y + w01 * d01.y;
                *(float2*)(Cf + (size_t)r0 * ldc + cc) = o0;
                float2 d10 = *(const float2*)&g_dres[(size_t)s10 * HD + cc];
                float2 d11 = *(const float2*)&g_dres[(size_t)s11 * HD + cc];
                float2 o1;
                o1.x = c[mi][ni][2] * sg1 + w10 * d10.x + w11 * d11.x;
                o1.y = c[mi][ni][3] * sg1 + w10 * d10.y + w11 * d11.y;
                *(float2*)(Cf + (size_t)r1 * ldc + cc) = o1;
            }
        }
    } else {                              // plain f32
        float* Cf = (float*)jb.C;
        #pragma unroll
        for (int mi = 0; mi < 4; mi++) {
            #pragma unroll
            for (int ni = 0; ni < 4; ni++) {
                int r  = m0 + wm0 + mi * 16 + gid;
                int cc = n0 + wn0 + ni * 8 + tg2;
                *(float2*)(Cf + (size_t)r * ldc + cc)       = make_float2(c[mi][ni][0], c[mi][ni][1]);
                *(float2*)(Cf + (size_t)(r + 8) * ldc + cc) = make_float2(c[mi][ni][2], c[mi][ni][3]);
            }
        }
    }
}

// ---------------- launch ----------------
extern "C" void kernel_launch(void* const* d_in, const int* in_sizes, int n_in,
                              void* d_out, int out_size) {
    const float* x    = (const float*)d_in[0];
    const float* gw   = (const float*)d_in[1];
    const float* gup  = (const float*)d_in[2];
    const float* down = (const float*)d_in[3];
    const float* sgp  = (const float*)d_in[4];
    const float* sup  = (const float*)d_in[5];
    const float* sdp  = (const float*)d_in[6];
    const float* segw = (const float*)d_in[7];
    float* out = (float*)d_out;
    int N = in_sizes[0] / HD;   // 8192

    __half *p_hbuf, *p_gbuf, *p_xh, *p_guph, *p_downh, *p_sguh, *p_sdph;
    float *p_dres;
    int *p_tok_idx, *p_blk_e;
    cudaGetSymbolAddress((void**)&p_hbuf,   g_hbufh);
    cudaGetSymbolAddress((void**)&p_dres,   g_dres);
    cudaGetSymbolAddress((void**)&p_gbuf,   g_gbufh);
    cudaGetSymbolAddress((void**)&p_xh,     g_xh);
    cudaGetSymbolAddress((void**)&p_guph,   g_guph);
    cudaGetSymbolAddress((void**)&p_downh,  g_downh);
    cudaGetSymbolAddress((void**)&p_sguh,   g_sguh);
    cudaGetSymbolAddress((void**)&p_sdph,   g_sdph);
    cudaGetSymbolAddress((void**)&p_tok_idx, g_tok_idx);
    cudaGetSymbolAddress((void**)&p_blk_e,  g_blk_e);

    cudaFuncSetAttribute(gemm_dual, cudaFuncAttributeMaxDynamicSharedMemorySize, SMEM_DYN);

    init_kernel<<<(SLOT_CAP + 255) / 256, 256>>>();
    router_kernel<<<(N + 7) / 8, 256>>>(x, gw, segw, N);
    offsets_kernel<<<1, 32>>>(out, (long)out_size - 1, N);
    assign_kernel<<<(N + 255) / 256, 256>>>(N);

    // conversions to fp16 (g/u row interleaving for fused silu)
    interleave_gup_kernel<<<(int)((long)NE*2*ID*HD/4/256), 256>>>(gup, p_guph);
    tohalf4<<<(int)((long)NE*HD*ID/4/256), 256>>>((const float4*)down, p_downh, (long)NE*HD*ID/4);
    interleave_sgu_kernel<<<(int)((long)2*ISD*HD/4/256), 256>>>(sgp, sup, p_sguh);
    tohalf4<<<(int)((long)HD*ISD/4/256), 256>>>((const float4*)sdp, p_sdph, (long)HD*ISD/4);
    tohalf4<<<(int)((long)N*HD/4/256), 256>>>((const float4*)x, p_xh, (long)N*HD/4);

    Job jz = {};  jz.nx = 1; jz.ny = 0;   // empty second job

    // Phase A: shared gate/up (64x32) + expert gate_up (144x8), both fused-silu
    Job jsgu = { p_xh, p_sguh, p_gbuf, HD, ISD, nullptr, nullptr, 0, 1, 0, N/128, ISD*2/128 };
    Job jegu = { p_xh, p_guph, p_hbuf, HD, ID,  p_tok_idx, p_blk_e, (long)2*ID*HD, 1, 1, MTILES, 2*ID/128 };
    int nbA0 = jsgu.nx * jsgu.ny;                 // 2048
    gemm_dual<<<nbA0 + jegu.nx * jegu.ny, 256, SMEM_DYN>>>(jsgu, jegu, nbA0);

    // Phase B: expert down (144x8) -> dres
    Job jed = { p_hbuf, p_downh, p_dres, ID, HD, nullptr, p_blk_e, (long)HD*ID, 0, 1, MTILES, HD/128 };
    gemm_dual<<<jed.nx * jed.ny, 256, SMEM_DYN>>>(jed, jz, jed.nx * jed.ny);

    // Phase C: shared down + fused final combine -> out
    Job jsd = { p_gbuf, p_sdph, out, ISD, HD, nullptr, nullptr, 0, 2, 0, N/128, HD/128 };
    gemm_dual<<<jsd.nx * jsd.ny, 256, SMEM_DYN>>>(jsd, jz, jsd.nx * jsd.ny);
}